// round 15
// baseline (speedup 1.0000x reference)
#include <cuda_runtime.h>
#include <cuda_fp16.h>
#include <stdint.h>

// WindowAttention, GB300. B_=4096 windows, N=49, H=8, hd=32, q=k=v=x.
// Round 15 = round 12 (champion) with two audit fixes:
//  - BRANCHLESS S-loop: always ldsm all 7 K tiles (removes 14 runtime-compare
//    branch regions per warp*rr; +2 ldsm, arithmetic bit-identical),
//  - fast precompute: 1 block per (w,h), smem-staged mask/rel/bias, 1 record/thread.
// fp16 S accumulators, constant-shift softmax (no max/shuffles),
// multiplicative fp16 table exp2(mask+bias), ones-MMA row sums,
// 512-thread CTAs (warp = head x rq-pair), 64-reg cap, 2 CTAs/SM.

#define NTOK 49
#define NHEAD 8
#define HD 32
#define DIMC 256
#define XSTR 264   // half stride per row (528B, 16B-aligned, ldmatrix conflict-free)
#define NPAD 64
#define RECS (4 * 7 * 32)   // uint2 records per (w,h): rq x nt x lane

// g_fused[(w*8+h)*RECS + (rq*7+nt)*32 + lane] = uint2
//  .x = half2(F(i0,j0), F(i0,j0+1)), .y = half2(F(i1,j0), F(i1,j0+1))
//  i0=16rq+(lane>>2), i1=i0+8, j0=nt*8+(lane&3)*2,
//  F(i,j) = exp2((mask[w,i,j] + bias_table[rel[i,j],h]) * log2e), 0 if OOB.
__device__ uint2 g_fused[64 * NHEAD * RECS];   // 3.67 MB, L2-resident

__global__ void __launch_bounds__(896)
precompute_fused(const float* __restrict__ bias_table,
                 const float* __restrict__ mask,
                 const int* __restrict__ rel) {
  // one block per (w,h); inputs staged once in smem, one record per thread
  const int w = blockIdx.x >> 3, h = blockIdx.x & 7;
  __shared__ float sm_mask[NTOK * NTOK];
  __shared__ float sm_bias[169];
  __shared__ uint8_t sm_rel[NTOK * NTOK];
  for (int i = threadIdx.x; i < NTOK * NTOK; i += 896) {
    sm_mask[i] = mask[w * NTOK * NTOK + i];
    sm_rel[i] = (uint8_t)rel[i];
  }
  if (threadIdx.x < 169) sm_bias[threadIdx.x] = bias_table[threadIdx.x * NHEAD + h];
  __syncthreads();

  const int p = threadIdx.x;               // 896 records per (w,h)
  const int rq = p / 224, rem = p - rq * 224;
  const int nt = rem >> 5, lane = rem & 31;
  const int g = lane >> 2, t = lane & 3;
  const int i0 = rq * 16 + g, i1 = i0 + 8, j0 = nt * 8 + t * 2;
  const float L2E = 1.4426950408889634f;
  float v[4];
#pragma unroll
  for (int q = 0; q < 4; q++) {
    int i = (q < 2) ? i0 : i1;
    int j = j0 + (q & 1);
    float val = 0.f;   // masked/OOB -> multiplicative 0 -> P' = 0
    if (i < NTOK && j < NTOK) {
      int ij = i * NTOK + j;
      val = exp2f((sm_mask[ij] + sm_bias[sm_rel[ij]]) * L2E);
    }
    v[q] = val;
  }
  uint2 r;
  __half2 a = __floats2half2_rn(v[0], v[1]);
  __half2 c = __floats2half2_rn(v[2], v[3]);
  r.x = *reinterpret_cast<uint32_t*>(&a);
  r.y = *reinterpret_cast<uint32_t*>(&c);
  g_fused[(size_t)blockIdx.x * RECS + p] = r;
}

// fp32-accumulator MMA (PV and row sums)
__device__ __forceinline__ void mma16816(float* c, const uint32_t* a, uint32_t b0, uint32_t b1) {
  asm volatile(
      "mma.sync.aligned.m16n8k16.row.col.f32.f16.f16.f32 "
      "{%0,%1,%2,%3},{%4,%5,%6,%7},{%8,%9},{%0,%1,%2,%3};\n"
      : "+f"(c[0]), "+f"(c[1]), "+f"(c[2]), "+f"(c[3])
      : "r"(a[0]), "r"(a[1]), "r"(a[2]), "r"(a[3]), "r"(b0), "r"(b1));
}
// fp16-accumulator MMA (S-GEMM): c[0] = h2(row g), c[1] = h2(row g+8)
__device__ __forceinline__ void mma16816h(uint32_t* c, const uint32_t* a, uint32_t b0, uint32_t b1) {
  asm volatile(
      "mma.sync.aligned.m16n8k16.row.col.f16.f16.f16.f16 "
      "{%0,%1},{%2,%3,%4,%5},{%6,%7},{%0,%1};\n"
      : "+r"(c[0]), "+r"(c[1])
      : "r"(a[0]), "r"(a[1]), "r"(a[2]), "r"(a[3]), "r"(b0), "r"(b1));
}

__device__ __forceinline__ void ldsm_x4(uint32_t* r, uint32_t addr) {
  asm volatile("ldmatrix.sync.aligned.m8n8.x4.shared.b16 {%0,%1,%2,%3},[%4];\n"
               : "=r"(r[0]), "=r"(r[1]), "=r"(r[2]), "=r"(r[3]) : "r"(addr));
}
__device__ __forceinline__ void ldsm_x4_t(uint32_t* r, uint32_t addr) {
  asm volatile("ldmatrix.sync.aligned.m8n8.x4.trans.shared.b16 {%0,%1,%2,%3},[%4];\n"
               : "=r"(r[0]), "=r"(r[1]), "=r"(r[2]), "=r"(r[3]) : "r"(addr));
}

__device__ __forceinline__ uint32_t h2ex2(uint32_t x) {
  uint32_t r;
  asm("ex2.approx.f16x2 %0, %1;\n" : "=r"(r) : "r"(x));
  return r;
}
__device__ __forceinline__ float rcpf(float x) {
  float r;
  asm("rcp.approx.ftz.f32 %0, %1;\n" : "=f"(r) : "f"(x));
  return r;
}
__device__ __forceinline__ uint32_t packh2(float a, float b) {
  __half2 h = __floats2half2_rn(a, b);
  return *reinterpret_cast<uint32_t*>(&h);
}
__device__ __forceinline__ uint32_t hmul2(uint32_t a, uint32_t b) {
  uint32_t d;
  asm("mul.f16x2 %0, %1, %2;\n" : "=r"(d) : "r"(a), "r"(b));
  return d;
}
__device__ __forceinline__ uint32_t hfma2(uint32_t a, uint32_t b, uint32_t c) {
  uint32_t d;
  asm("fma.rn.f16x2 %0, %1, %2, %3;\n" : "=r"(d) : "r"(a), "r"(b), "r"(c));
  return d;
}

__global__ void __launch_bounds__(512, 2)
winattn_kernel(const float* __restrict__ x, float* __restrict__ out) {
  __shared__ __half xh[NPAD * XSTR];   // 33792 B; 2 CTAs/SM
  const int tid = threadIdx.x;
  const int b = blockIdx.x;
  const int w = b & 63;

  // ---- fill: x -> fp16 plane (float4 loads), zero pad rows 49..63 ----
  {
    uint4* p = reinterpret_cast<uint4*>(xh + NTOK * XSTR);
    const int n128 = (NPAD - NTOK) * XSTR / 8;
    for (int i = tid; i < n128; i += 512) p[i] = make_uint4(0u, 0u, 0u, 0u);
  }
  {
    const float4* x4 = reinterpret_cast<const float4*>(x) + (size_t)b * NTOK * (DIMC / 4);
    for (int idx = tid; idx < NTOK * (DIMC / 4); idx += 512) {
      int r = idx >> 6, c4 = idx & 63;
      float4 v = x4[idx];
      uint2 pk;
      pk.x = packh2(v.x, v.y);
      pk.y = packh2(v.z, v.w);
      *reinterpret_cast<uint2*>(xh + r * XSTR + c4 * 4) = pk;
    }
  }
  __syncthreads();

  const int lane = tid & 31;
  const int t = lane & 3;
  const int g = lane >> 2;
  const int warp = tid >> 5;
  const int h = warp & 7;
  const int rqh = warp >> 3;               // 0: rq {0,1}, 1: rq {2,3}
  const int lr = lane & 7, lm = lane >> 3;
  const uint32_t smbase = (uint32_t)__cvta_generic_to_shared(xh);
  const uint2* fptr = g_fused + (size_t)(w * NHEAD + h) * RECS + lane;
  float* outb = out + (size_t)b * NTOK * DIMC + h * HD;
  __half2 sl2e_h = __float2half2_rn(0.25503480f);    // 32^-0.5 * log2(e)
  const uint32_t SL2E2 = *reinterpret_cast<uint32_t*>(&sl2e_h);
  const uint32_t NC8 = 0xC800C800u;        // half2(-8,-8): constant softmax shift
  const uint32_t ONES = 0x3C003C00u;       // half2(1,1) for the row-sum MMA

#pragma unroll 1
  for (int rr = 0; rr < 2; rr++) {
    const int rq = rqh * 2 + rr;
    const int q0 = rq << 4;
    const int i0 = q0 + g, i1 = i0 + 8;

    // Q A-fragments (2 ldsm); K tiles are loaded independently below (branchless)
    uint32_t kq0[4], kq1[4];
    ldsm_x4(kq0, smbase + (((q0 + lr) * XSTR + h * HD + lm * 8) << 1));
    ldsm_x4(kq1, smbase + (((q0 + 8 + lr) * XSTR + h * HD + lm * 8) << 1));
    uint32_t qa0[4] = {kq0[0], kq1[0], kq0[1], kq1[1]};   // k 0..15
    uint32_t qa1[4] = {kq0[2], kq1[2], kq0[3], kq1[3]};   // k 16..31

    // multiplicative-table prefetch: 7 x LDG.64, consumed only after exp
    uint2 fz[7];
#pragma unroll
    for (int nt = 0; nt < 7; nt++) fz[nt] = fptr[(rq * 7 + nt) * 32];

    // S accumulators in fp16: sch[nt] = { h2(i0: j0,j0+1), h2(i1: j0,j0+1) }
    uint32_t sch[7][2];
#pragma unroll
    for (int i = 0; i < 7; i++) { sch[i][0] = 0u; sch[i][1] = 0u; }

    // S = q @ k^T (fp16 acc); BRANCHLESS: always load K tile (no diag compares)
#pragma unroll
    for (int nt = 0; nt < 7; nt++) {
      uint32_t kb[4];
      ldsm_x4(kb, smbase + (((nt * 8 + lr) * XSTR + h * HD + lm * 8) << 1));
      mma16816h(sch[nt], qa0, kb[0], kb[1]);
      mma16816h(sch[nt], qa1, kb[2], kb[3]);
    }

    // P' = 2^(qk*SL2E - 8) * F  — constant shift, no row max, no shuffles.
    // (normalization by the ones-MMA sum of the SAME P' cancels the shift)
#pragma unroll
    for (int nt = 0; nt < 7; nt++) {
      sch[nt][0] = hmul2(h2ex2(hfma2(sch[nt][0], SL2E2, NC8)), fz[nt].x);
      sch[nt][1] = hmul2(h2ex2(hfma2(sch[nt][1], SL2E2, NC8)), fz[nt].y);
    }

    // O = P' @ V and su = P' @ ones (tensor pipe, overlapped)
    float oc[4][4];
#pragma unroll
    for (int i = 0; i < 4; i++)
#pragma unroll
      for (int k = 0; k < 4; k++) oc[i][k] = 0.f;
    float su[4] = {0.f, 0.f, 0.f, 0.f};

#pragma unroll
    for (int kt = 0; kt < 4; kt++) {
      uint32_t pa[4];
      pa[0] = sch[2 * kt][0];
      pa[1] = sch[2 * kt][1];
      pa[2] = (kt < 3) ? sch[2 * kt + 1][0] : 0u;   // j>=56: P = 0
      pa[3] = (kt < 3) ? sch[2 * kt + 1][1] : 0u;
      mma16816(su, pa, ONES, ONES);                 // full row sums in every lane
#pragma unroll
      for (int ntb = 0; ntb < 2; ntb++) {
        uint32_t vfr[4];
        uint32_t a = smbase +
            (((kt * 16 + ((lm & 1) << 3) + lr) * XSTR + h * HD + (ntb * 2 + (lm >> 1)) * 8) << 1);
        ldsm_x4_t(vfr, a);
        mma16816(oc[ntb * 2 + 0], pa, vfr[0], vfr[1]);
        mma16816(oc[ntb * 2 + 1], pa, vfr[2], vfr[3]);
      }
    }
    const float rn0 = rcpf(su[0]), rn1 = rcpf(su[2]);

    // normalize in fp32 at store time (pad rows never stored)
    if (i0 < NTOK) {
#pragma unroll
      for (int c = 0; c < 4; c++) {
        float2 v; v.x = oc[c][0] * rn0; v.y = oc[c][1] * rn0;
        *reinterpret_cast<float2*>(outb + (size_t)i0 * DIMC + c * 8 + t * 2) = v;
      }
    }
    if (i1 < NTOK) {
#pragma unroll
      for (int c = 0; c < 4; c++) {
        float2 v; v.x = oc[c][2] * rn1; v.y = oc[c][3] * rn1;
        *reinterpret_cast<float2*>(outb + (size_t)i1 * DIMC + c * 8 + t * 2) = v;
      }
    }
  }
}

extern "C" void kernel_launch(void* const* d_in, const int* in_sizes, int n_in,
                              void* d_out, int out_size) {
  (void)in_sizes; (void)n_in; (void)out_size;
  const float* x = (const float*)d_in[0];
  const float* bias_table = (const float*)d_in[1];
  const float* mask = (const float*)d_in[2];
  const int* rel = (const int*)d_in[3];
  float* out = (float*)d_out;

  precompute_fused<<<64 * NHEAD, 896>>>(bias_table, mask, rel);
  winattn_kernel<<<4096, 512>>>(x, out);
}

// round 16
// speedup vs baseline: 1.0286x; 1.0286x over previous
#include <cuda_runtime.h>
#include <cuda_fp16.h>
#include <stdint.h>

// WindowAttention, GB300. B_=4096 windows, N=49, H=8, hd=32, q=k=v=x.
// Round 16 = round 12 (champion) with the S/PV loops FUSED per tile-pair:
//  constant-shift softmax has no cross-tile dependency, so each kt iteration
//  loads 2 K tiles, computes S, exps to P', and reuses the SAME kb registers
//  as V B-operands via movmatrix (in-register transpose) -> ldsm/rr 17 -> 9.
// fp16 S accumulators, multiplicative fp16 table exp2(mask+bias),
// ones-MMA row sums, 512-thread CTAs (warp = head x rq-pair), 64-reg cap.

#define NTOK 49
#define NHEAD 8
#define HD 32
#define DIMC 256
#define XSTR 264   // half stride per row (528B, 16B-aligned, ldmatrix conflict-free)
#define NPAD 64
#define RECS (4 * 7 * 32)   // uint2 records per (w,h): rq x nt x lane

// g_fused[(w*8+h)*RECS + (rq*7+nt)*32 + lane] = uint2
//  .x = half2(F(i0,j0), F(i0,j0+1)), .y = half2(F(i1,j0), F(i1,j0+1))
//  i0=16rq+(lane>>2), i1=i0+8, j0=nt*8+(lane&3)*2,
//  F(i,j) = exp2((mask[w,i,j] + bias_table[rel[i,j],h]) * log2e), 0 if OOB.
__device__ uint2 g_fused[64 * NHEAD * RECS];   // 3.67 MB, L2-resident

__global__ void __launch_bounds__(256)
precompute_fused(const float* __restrict__ bias_table,
                 const float* __restrict__ mask,
                 const int* __restrict__ rel) {
  const int p = blockIdx.x * 256 + threadIdx.x;   // 1792*256 = 458752 records
  const int wh = p / RECS;
  const int rec = p - wh * RECS;
  const int w = wh >> 3, h = wh & 7;
  const int rq = rec / 224, rem = rec - rq * 224;
  const int nt = rem >> 5, lane = rem & 31;
  const int g = lane >> 2, t = lane & 3;
  const int i0 = rq * 16 + g, i1 = i0 + 8, j0 = nt * 8 + t * 2;
  const float L2E = 1.4426950408889634f;
  float v[4];
#pragma unroll
  for (int q = 0; q < 4; q++) {
    int i = (q < 2) ? i0 : i1;
    int j = j0 + (q & 1);
    float val = 0.f;   // masked/OOB -> multiplicative 0 -> P' = 0
    if (i < NTOK && j < NTOK) {
      int ij = i * NTOK + j;
      val = exp2f((mask[w * NTOK * NTOK + ij] + bias_table[rel[ij] * NHEAD + h]) * L2E);
    }
    v[q] = val;
  }
  uint2 r;
  __half2 a = __floats2half2_rn(v[0], v[1]);
  __half2 c = __floats2half2_rn(v[2], v[3]);
  r.x = *reinterpret_cast<uint32_t*>(&a);
  r.y = *reinterpret_cast<uint32_t*>(&c);
  g_fused[p] = r;
}

// fp32-accumulator MMA (PV and row sums)
__device__ __forceinline__ void mma16816(float* c, const uint32_t* a, uint32_t b0, uint32_t b1) {
  asm volatile(
      "mma.sync.aligned.m16n8k16.row.col.f32.f16.f16.f32 "
      "{%0,%1,%2,%3},{%4,%5,%6,%7},{%8,%9},{%0,%1,%2,%3};\n"
      : "+f"(c[0]), "+f"(c[1]), "+f"(c[2]), "+f"(c[3])
      : "r"(a[0]), "r"(a[1]), "r"(a[2]), "r"(a[3]), "r"(b0), "r"(b1));
}
// fp16-accumulator MMA (S-GEMM): c[0] = h2(row g), c[1] = h2(row g+8)
__device__ __forceinline__ void mma16816h(uint32_t* c, const uint32_t* a, uint32_t b0, uint32_t b1) {
  asm volatile(
      "mma.sync.aligned.m16n8k16.row.col.f16.f16.f16.f16 "
      "{%0,%1},{%2,%3,%4,%5},{%6,%7},{%0,%1};\n"
      : "+r"(c[0]), "+r"(c[1])
      : "r"(a[0]), "r"(a[1]), "r"(a[2]), "r"(a[3]), "r"(b0), "r"(b1));
}

__device__ __forceinline__ void ldsm_x4(uint32_t* r, uint32_t addr) {
  asm volatile("ldmatrix.sync.aligned.m8n8.x4.shared.b16 {%0,%1,%2,%3},[%4];\n"
               : "=r"(r[0]), "=r"(r[1]), "=r"(r[2]), "=r"(r[3]) : "r"(addr));
}
__device__ __forceinline__ uint32_t movm_t(uint32_t a) {
  uint32_t d;
  asm volatile("movmatrix.sync.aligned.m8n8.trans.b16 %0, %1;\n" : "=r"(d) : "r"(a));
  return d;
}

__device__ __forceinline__ uint32_t h2ex2(uint32_t x) {
  uint32_t r;
  asm("ex2.approx.f16x2 %0, %1;\n" : "=r"(r) : "r"(x));
  return r;
}
__device__ __forceinline__ float rcpf(float x) {
  float r;
  asm("rcp.approx.ftz.f32 %0, %1;\n" : "=f"(r) : "f"(x));
  return r;
}
__device__ __forceinline__ uint32_t packh2(float a, float b) {
  __half2 h = __floats2half2_rn(a, b);
  return *reinterpret_cast<uint32_t*>(&h);
}
__device__ __forceinline__ uint32_t hmul2(uint32_t a, uint32_t b) {
  uint32_t d;
  asm("mul.f16x2 %0, %1, %2;\n" : "=r"(d) : "r"(a), "r"(b));
  return d;
}
__device__ __forceinline__ uint32_t hfma2(uint32_t a, uint32_t b, uint32_t c) {
  uint32_t d;
  asm("fma.rn.f16x2 %0, %1, %2, %3;\n" : "=r"(d) : "r"(a), "r"(b), "r"(c));
  return d;
}

__global__ void __launch_bounds__(512, 2)
winattn_kernel(const float* __restrict__ x, float* __restrict__ out) {
  __shared__ __half xh[NPAD * XSTR];   // 33792 B; 2 CTAs/SM
  const int tid = threadIdx.x;
  const int b = blockIdx.x;
  const int w = b & 63;

  // ---- fill: x -> fp16 plane (float4 loads), zero pad rows 49..63 ----
  {
    uint4* p = reinterpret_cast<uint4*>(xh + NTOK * XSTR);
    const int n128 = (NPAD - NTOK) * XSTR / 8;
    for (int i = tid; i < n128; i += 512) p[i] = make_uint4(0u, 0u, 0u, 0u);
  }
  {
    const float4* x4 = reinterpret_cast<const float4*>(x) + (size_t)b * NTOK * (DIMC / 4);
    for (int idx = tid; idx < NTOK * (DIMC / 4); idx += 512) {
      int r = idx >> 6, c4 = idx & 63;
      float4 v = x4[idx];
      uint2 pk;
      pk.x = packh2(v.x, v.y);
      pk.y = packh2(v.z, v.w);
      *reinterpret_cast<uint2*>(xh + r * XSTR + c4 * 4) = pk;
    }
  }
  __syncthreads();

  const int lane = tid & 31;
  const int t = lane & 3;
  const int g = lane >> 2;
  const int warp = tid >> 5;
  const int h = warp & 7;
  const int rqh = warp >> 3;               // 0: rq {0,1}, 1: rq {2,3}
  const int lr = lane & 7, lm = lane >> 3;
  const uint32_t smbase = (uint32_t)__cvta_generic_to_shared(xh);
  const uint2* fptr = g_fused + (size_t)(w * NHEAD + h) * RECS + lane;
  float* outb = out + (size_t)b * NTOK * DIMC + h * HD;
  __half2 sl2e_h = __float2half2_rn(0.25503480f);    // 32^-0.5 * log2(e)
  const uint32_t SL2E2 = *reinterpret_cast<uint32_t*>(&sl2e_h);
  const uint32_t NC8 = 0xC800C800u;        // half2(-8,-8): constant softmax shift
  const uint32_t ONES = 0x3C003C00u;       // half2(1,1) for the row-sum MMA

#pragma unroll 1
  for (int rr = 0; rr < 2; rr++) {
    const int rq = rqh * 2 + rr;
    const int q0 = rq << 4;
    const int i0 = q0 + g, i1 = i0 + 8;

    // Q A-fragments (2 ldsm)
    uint32_t kq0[4], kq1[4];
    ldsm_x4(kq0, smbase + (((q0 + lr) * XSTR + h * HD + lm * 8) << 1));
    ldsm_x4(kq1, smbase + (((q0 + 8 + lr) * XSTR + h * HD + lm * 8) << 1));
    uint32_t qa0[4] = {kq0[0], kq1[0], kq0[1], kq1[1]};   // k 0..15
    uint32_t qa1[4] = {kq0[2], kq1[2], kq0[3], kq1[3]};   // k 16..31

    // multiplicative-table prefetch: 7 x LDG.64 (consumed after each tile's exp)
    uint2 fz[7];
#pragma unroll
    for (int nt = 0; nt < 7; nt++) fz[nt] = fptr[(rq * 7 + nt) * 32];

    // fused S + softmax + PV per tile-pair; kb reused as V via movmatrix
    float oc[4][4];
#pragma unroll
    for (int i = 0; i < 4; i++)
#pragma unroll
      for (int k = 0; k < 4; k++) oc[i][k] = 0.f;
    float su[4] = {0.f, 0.f, 0.f, 0.f};

#pragma unroll
    for (int kt = 0; kt < 4; kt++) {
      const int n0 = 2 * kt, n1 = n0 + 1;   // n1==7 at kt=3: zero pad tile
      uint32_t kb0[4], kb1[4];
      ldsm_x4(kb0, smbase + (((n0 * 8 + lr) * XSTR + h * HD + lm * 8) << 1));
      if (kt < 3)
        ldsm_x4(kb1, smbase + (((n1 * 8 + lr) * XSTR + h * HD + lm * 8) << 1));

      // S for the two 8-col tiles (fp16 acc)
      uint32_t s0[2] = {0u, 0u}, s1[2] = {0u, 0u};
      mma16816h(s0, qa0, kb0[0], kb0[1]);
      mma16816h(s0, qa1, kb0[2], kb0[3]);
      if (kt < 3) {
        mma16816h(s1, qa0, kb1[0], kb1[1]);
        mma16816h(s1, qa1, kb1[2], kb1[3]);
      }

      // P' = 2^(qk*SL2E - 8) * F  (constant shift; sum-normalization cancels it)
      uint32_t pa[4];
      pa[0] = hmul2(h2ex2(hfma2(s0[0], SL2E2, NC8)), fz[n0].x);
      pa[1] = hmul2(h2ex2(hfma2(s0[1], SL2E2, NC8)), fz[n0].y);
      pa[2] = (kt < 3) ? hmul2(h2ex2(hfma2(s1[0], SL2E2, NC8)), fz[n1].x) : 0u;
      pa[3] = (kt < 3) ? hmul2(h2ex2(hfma2(s1[1], SL2E2, NC8)), fz[n1].y) : 0u;

      // row sums + PV; V B-frags = movmatrix transpose of the SAME kb registers
      mma16816(su, pa, ONES, ONES);
#pragma unroll
      for (int c = 0; c < 4; c++) {
        uint32_t b0 = movm_t(kb0[c]);
        uint32_t b1 = (kt < 3) ? movm_t(kb1[c]) : 0u;
        mma16816(oc[c], pa, b0, b1);
      }
    }
    const float rn0 = rcpf(su[0]), rn1 = rcpf(su[2]);

    // normalize in fp32 at store time (pad rows never stored)
    if (i0 < NTOK) {
#pragma unroll
      for (int c = 0; c < 4; c++) {
        float2 v; v.x = oc[c][0] * rn0; v.y = oc[c][1] * rn0;
        *reinterpret_cast<float2*>(outb + (size_t)i0 * DIMC + c * 8 + t * 2) = v;
      }
    }
    if (i1 < NTOK) {
#pragma unroll
      for (int c = 0; c < 4; c++) {
        float2 v; v.x = oc[c][2] * rn1; v.y = oc[c][3] * rn1;
        *reinterpret_cast<float2*>(outb + (size_t)i1 * DIMC + c * 8 + t * 2) = v;
      }
    }
  }
}

extern "C" void kernel_launch(void* const* d_in, const int* in_sizes, int n_in,
                              void* d_out, int out_size) {
  (void)in_sizes; (void)n_in; (void)out_size;
  const float* x = (const float*)d_in[0];
  const float* bias_table = (const float*)d_in[1];
  const float* mask = (const float*)d_in[2];
  const int* rel = (const int*)d_in[3];
  float* out = (float*)d_out;

  precompute_fused<<<1792, 256>>>(bias_table, mask, rel);
  winattn_kernel<<<4096, 512>>>(x, out);
}